// round 3
// baseline (speedup 1.0000x reference)
#include <cuda_runtime.h>
#include <cuda_bf16.h>
#include <cstdint>
#include <cstdio>

// ---------------------------------------------------------------------------
// Problem constants (match reference setup_inputs)
// ---------------------------------------------------------------------------
#define NN      50000     // nodes
#define EE      500000    // edges
#define GG      50        // graphs
#define NPG     1000      // nodes per graph
#define INDIM   128
#define HH      4         // heads
#define D1      64        // hidden 1
#define D2      128       // hidden 2
#define SLOPE   0.2f

// ---------------------------------------------------------------------------
// Scratch (static __device__ globals; no allocations allowed)
// ---------------------------------------------------------------------------
__device__ float g_fs1[NN * HH * D1];     // 51.2 MB
__device__ float g_fd1[NN * HH * D1];     // 51.2 MB
__device__ float g_h1 [NN * D1];          // 12.8 MB
__device__ float g_fs2[NN * HH * D2];     // 102.4 MB
__device__ float g_fd2[NN * HH * D2];     // 102.4 MB
__device__ float g_h2 [NN * D2];          // 25.6 MB
__device__ float g_logits[EE * HH];       // 8 MB
__device__ float g_gate[NN];

__device__ int g_counts[NN];
__device__ int g_incl[NN];
__device__ int g_bsum[64];
__device__ int g_boff[64];
__device__ int g_indptr[NN + 1];
__device__ int g_cursor[NN];
__device__ int g_eid[EE];

// ---------------------------------------------------------------------------
// SGEMM: C[M,Nn] = A[M,K] @ B[K,Nn] + bias[Nn]
// BM=BN=128, BK=16, 256 threads, 8x8 microtile. Nn % 128 == 0, K % 16 == 0.
// ---------------------------------------------------------------------------
__global__ __launch_bounds__(256) void sgemm_bias_kernel(
    const float* __restrict__ A, const float* __restrict__ B,
    const float* __restrict__ bias, float* __restrict__ C,
    int M, int Nn, int K)
{
    __shared__ float As[16][128];
    __shared__ float Bs[16][128];

    const int tid = threadIdx.x;
    const int tx = tid & 15;          // 0..15  (N dir)
    const int ty = tid >> 4;          // 0..15  (M dir)
    const int row0 = blockIdx.y * 128;
    const int col0 = blockIdx.x * 128;

    float acc[8][8];
#pragma unroll
    for (int i = 0; i < 8; i++)
#pragma unroll
        for (int j = 0; j < 8; j++) acc[i][j] = 0.f;

    for (int k0 = 0; k0 < K; k0 += 16) {
        // load A tile: 128 rows x 16 k  (512 float4, 2 per thread)
#pragma unroll
        for (int r = 0; r < 2; r++) {
            int v = tid + r * 256;
            int m = v >> 2, kq = v & 3;
            int grow = row0 + m;
            float4 val = make_float4(0.f, 0.f, 0.f, 0.f);
            if (grow < M)
                val = *(const float4*)&A[(size_t)grow * K + k0 + kq * 4];
            As[kq * 4 + 0][m] = val.x;
            As[kq * 4 + 1][m] = val.y;
            As[kq * 4 + 2][m] = val.z;
            As[kq * 4 + 3][m] = val.w;
        }
        // load B tile: 16 k x 128 cols (512 float4, 2 per thread)
#pragma unroll
        for (int r = 0; r < 2; r++) {
            int v = tid + r * 256;
            int k = v >> 5, nq = v & 31;
            *(float4*)&Bs[k][nq * 4] =
                *(const float4*)&B[(size_t)(k0 + k) * Nn + col0 + nq * 4];
        }
        __syncthreads();

#pragma unroll
        for (int kk = 0; kk < 16; kk++) {
            float a[8], b[8];
            *(float4*)&a[0] = *(const float4*)&As[kk][ty * 8];
            *(float4*)&a[4] = *(const float4*)&As[kk][ty * 8 + 4];
            *(float4*)&b[0] = *(const float4*)&Bs[kk][tx * 8];
            *(float4*)&b[4] = *(const float4*)&Bs[kk][tx * 8 + 4];
#pragma unroll
            for (int i = 0; i < 8; i++)
#pragma unroll
                for (int j = 0; j < 8; j++) acc[i][j] += a[i] * b[j];
        }
        __syncthreads();
    }

#pragma unroll
    for (int i = 0; i < 8; i++) {
        int grow = row0 + ty * 8 + i;
        if (grow >= M) break;
#pragma unroll
        for (int j = 0; j < 8; j++) {
            int gcol = col0 + tx * 8 + j;
            C[(size_t)grow * Nn + gcol] = acc[i][j] + bias[gcol];
        }
    }
}

// ---------------------------------------------------------------------------
// CSR build by destination node
// ---------------------------------------------------------------------------
__global__ void zero_counts_kernel(int n) {
    int i = blockIdx.x * blockDim.x + threadIdx.x;
    if (i < n) g_counts[i] = 0;
}

__global__ void hist_kernel(const int* __restrict__ dst, int E) {
    int e = blockIdx.x * blockDim.x + threadIdx.x;
    if (e < E) atomicAdd(&g_counts[dst[e]], 1);
}

__global__ __launch_bounds__(1024) void scan_block_kernel(int n) {
    __shared__ int s[1024];
    int i = blockIdx.x * 1024 + threadIdx.x;
    s[threadIdx.x] = (i < n) ? g_counts[i] : 0;
    __syncthreads();
    for (int off = 1; off < 1024; off <<= 1) {
        int x = 0;
        if (threadIdx.x >= off) x = s[threadIdx.x - off];
        __syncthreads();
        s[threadIdx.x] += x;
        __syncthreads();
    }
    if (i < n) g_incl[i] = s[threadIdx.x];
    if (threadIdx.x == 1023) g_bsum[blockIdx.x] = s[1023];
}

__global__ void scan_bsum_kernel(int nb) {
    if (threadIdx.x == 0 && blockIdx.x == 0) {
        int acc = 0;
        for (int b = 0; b < nb; b++) { g_boff[b] = acc; acc += g_bsum[b]; }
    }
}

__global__ void finalize_indptr_kernel(int n) {
    int i = blockIdx.x * blockDim.x + threadIdx.x;
    if (i < n) {
        int v = g_incl[i] + g_boff[i >> 10];
        g_indptr[i + 1] = v;
        g_cursor[i + 1 <= n ? 0 : 0] = g_cursor[0]; // no-op guard (kept simple)
    }
    if (i == 0) g_indptr[0] = 0;
}

__global__ void copy_cursor_kernel(int n) {
    int i = blockIdx.x * blockDim.x + threadIdx.x;
    if (i < n) g_cursor[i] = g_indptr[i];
}

__global__ void scatter_kernel(const int* __restrict__ dst, int E) {
    int e = blockIdx.x * blockDim.x + threadIdx.x;
    if (e < E) {
        int slot = atomicAdd(&g_cursor[dst[e]], 1);
        g_eid[slot] = e;
    }
}

// ---------------------------------------------------------------------------
// Per-edge GATv2 logits: logit[e,h] = sum_d attn[h,d] * leakyrelu(fs[src]+fd[dst])
// One warp per edge.
// ---------------------------------------------------------------------------
template <int D>
__global__ __launch_bounds__(256) void edge_logits_kernel(
    const float* __restrict__ fs, const float* __restrict__ fd,
    const int* __restrict__ src, const int* __restrict__ dst,
    const float* __restrict__ attn, float* __restrict__ logits, int E)
{
    int warp = (blockIdx.x * blockDim.x + threadIdx.x) >> 5;
    int lane = threadIdx.x & 31;
    if (warp >= E) return;
    const float* ps = fs + (size_t)src[warp] * (HH * D);
    const float* pd = fd + (size_t)dst[warp] * (HH * D);
#pragma unroll
    for (int h = 0; h < HH; h++) {
        float p = 0.f;
#pragma unroll
        for (int d = lane; d < D; d += 32) {
            float v = ps[h * D + d] + pd[h * D + d];
            v = v > 0.f ? v : SLOPE * v;
            p += attn[h * D + d] * v;
        }
#pragma unroll
        for (int o = 16; o; o >>= 1) p += __shfl_down_sync(0xffffffffu, p, o);
        if (lane == 0) logits[(size_t)warp * HH + h] = p;
    }
}

// ---------------------------------------------------------------------------
// Per-dst-node: edge softmax (max, sum) + weighted aggregation + head max-pool.
// One block per node, HH*D threads. No atomics (CSR edge list).
// ---------------------------------------------------------------------------
template <int D>
__global__ void gat_aggregate_kernel(
    const float* __restrict__ fs, const float* __restrict__ logits,
    const int* __restrict__ edge_src, float* __restrict__ hout)
{
    const int n = blockIdx.x;
    const int t = threadIdx.x;            // 0 .. HH*D-1
    const int h = t / D;

    __shared__ float sm[HH], sinv[HH];
    __shared__ int   ssrc[32];
    __shared__ float sw[32][HH];
    __shared__ float redbuf[HH * D];

    const int beg = g_indptr[n];
    const int deg = g_indptr[n + 1] - beg;

    if (t < HH) {
        float mm = -1e30f;
        for (int i = 0; i < deg; i++)
            mm = fmaxf(mm, logits[(size_t)g_eid[beg + i] * HH + t]);
        float ss = 0.f;
        for (int i = 0; i < deg; i++)
            ss += __expf(logits[(size_t)g_eid[beg + i] * HH + t] - mm);
        sm[t] = mm;
        sinv[t] = deg > 0 ? 1.f / ss : 0.f;
    }
    __syncthreads();

    float acc = 0.f;
    for (int c = 0; c < deg; c += 32) {
        int cnt = min(32, deg - c);
        if (t < cnt) ssrc[t] = edge_src[g_eid[beg + c + t]];
        if (t < cnt * HH) {
            int i = t >> 2, hh = t & 3;
            float lg = logits[(size_t)g_eid[beg + c + i] * HH + hh];
            sw[i][hh] = __expf(lg - sm[hh]) * sinv[hh];
        }
        __syncthreads();
        for (int i = 0; i < cnt; i++)
            acc += sw[i][h] * fs[(size_t)ssrc[i] * (HH * D) + t];
        __syncthreads();
    }

    redbuf[t] = acc;
    __syncthreads();
    if (t < D) {
        float mx = redbuf[t];
#pragma unroll
        for (int hh = 1; hh < HH; hh++) mx = fmaxf(mx, redbuf[hh * D + t]);
        hout[(size_t)n * D + t] = mx;
    }
}

// ---------------------------------------------------------------------------
// Gate: gate[n] = h2[n,:] . gate_w + gate_b   (one warp per node)
// ---------------------------------------------------------------------------
__global__ __launch_bounds__(256) void gate_kernel(
    const float* __restrict__ h2, const float* __restrict__ gw,
    const float* __restrict__ gb, int N)
{
    int warp = (blockIdx.x * blockDim.x + threadIdx.x) >> 5;
    int lane = threadIdx.x & 31;
    if (warp >= N) return;
    const float* p2 = h2 + (size_t)warp * D2;
    float p = 0.f;
#pragma unroll
    for (int d = lane; d < D2; d += 32) p += p2[d] * gw[d];
#pragma unroll
    for (int o = 16; o; o >>= 1) p += __shfl_down_sync(0xffffffffu, p, o);
    if (lane == 0) g_gate[warp] = p + gb[0];
}

// ---------------------------------------------------------------------------
// Global attention pooling: one block per graph (1000 contiguous nodes).
// ---------------------------------------------------------------------------
__global__ __launch_bounds__(256) void pool_kernel(
    const float* __restrict__ h2, float* __restrict__ out)
{
    const int g = blockIdx.x;
    const int t = threadIdx.x;       // 256
    __shared__ float red[256];
    __shared__ float w[NPG];
    const int base = g * NPG;

    float mm = -1e30f;
    for (int i = t; i < NPG; i += 256) mm = fmaxf(mm, g_gate[base + i]);
    red[t] = mm;
    __syncthreads();
    for (int o = 128; o; o >>= 1) {
        if (t < o) red[t] = fmaxf(red[t], red[t + o]);
        __syncthreads();
    }
    float gmax = red[0];
    __syncthreads();

    float ss = 0.f;
    for (int i = t; i < NPG; i += 256) {
        float e = __expf(g_gate[base + i] - gmax);
        w[i] = e;
        ss += e;
    }
    red[t] = ss;
    __syncthreads();
    for (int o = 128; o; o >>= 1) {
        if (t < o) red[t] += red[t + o];
        __syncthreads();
    }
    float inv = 1.f / red[0];
    __syncthreads();

    if (t < D2) {
        float acc = 0.f;
        for (int i = 0; i < NPG; i++)
            acc += w[i] * h2[(size_t)(base + i) * D2 + t];
        out[g * D2 + t] = acc * inv;
    }
}

// ---------------------------------------------------------------------------
// Launch
// ---------------------------------------------------------------------------
extern "C" void kernel_launch(void* const* d_in, const int* in_sizes, int n_in,
                              void* d_out, int out_size)
{
    const float* x     = (const float*)d_in[0];
    const int*   esrc  = (const int*)  d_in[1];
    const int*   edst  = (const int*)  d_in[2];
    // d_in[3] = node_graph (implicit: n / NPG)
    const float* Wl1   = (const float*)d_in[4];
    const float* bl1   = (const float*)d_in[5];
    const float* Wr1   = (const float*)d_in[6];
    const float* br1   = (const float*)d_in[7];
    const float* attn1 = (const float*)d_in[8];
    const float* Wl2   = (const float*)d_in[9];
    const float* bl2   = (const float*)d_in[10];
    const float* Wr2   = (const float*)d_in[11];
    const float* br2   = (const float*)d_in[12];
    const float* attn2 = (const float*)d_in[13];
    const float* gw    = (const float*)d_in[14];
    const float* gb    = (const float*)d_in[15];
    float* out = (float*)d_out;

    float *fs1, *fd1, *h1, *fs2, *fd2, *h2, *logits;
    cudaGetSymbolAddress((void**)&fs1, g_fs1);
    cudaGetSymbolAddress((void**)&fd1, g_fd1);
    cudaGetSymbolAddress((void**)&h1,  g_h1);
    cudaGetSymbolAddress((void**)&fs2, g_fs2);
    cudaGetSymbolAddress((void**)&fd2, g_fd2);
    cudaGetSymbolAddress((void**)&h2,  g_h2);
    cudaGetSymbolAddress((void**)&logits, g_logits);
    float* gate;
    cudaGetSymbolAddress((void**)&gate, g_gate);

    const int M = NN;
    const dim3 gemm_block(256);

    // ---- CSR build (shared by both layers; same edge list) ----
    zero_counts_kernel<<<(NN + 255) / 256, 256>>>(NN);
    hist_kernel<<<(EE + 255) / 256, 256>>>(edst, EE);
    int nb = (NN + 1023) / 1024;
    scan_block_kernel<<<nb, 1024>>>(NN);
    scan_bsum_kernel<<<1, 32>>>(nb);
    finalize_indptr_kernel<<<(NN + 255) / 256, 256>>>(NN);
    copy_cursor_kernel<<<(NN + 255) / 256, 256>>>(NN);
    scatter_kernel<<<(EE + 255) / 256, 256>>>(edst, EE);

    // ---- Layer 1 ----
    {
        const int Nn = HH * D1;  // 256
        dim3 grid(Nn / 128, (M + 127) / 128);
        sgemm_bias_kernel<<<grid, gemm_block>>>(x, Wl1, bl1, fs1, M, Nn, INDIM);
        sgemm_bias_kernel<<<grid, gemm_block>>>(x, Wr1, br1, fd1, M, Nn, INDIM);
        edge_logits_kernel<D1><<<EE / 8, 256>>>(fs1, fd1, esrc, edst, attn1, logits, EE);
        gat_aggregate_kernel<D1><<<NN, HH * D1>>>(fs1, logits, esrc, h1);
    }

    // ---- Layer 2 ----
    {
        const int Nn = HH * D2;  // 512
        dim3 grid(Nn / 128, (M + 127) / 128);
        sgemm_bias_kernel<<<grid, gemm_block>>>(h1, Wl2, bl2, fs2, M, Nn, D1);
        sgemm_bias_kernel<<<grid, gemm_block>>>(h1, Wr2, br2, fd2, M, Nn, D1);
        edge_logits_kernel<D2><<<EE / 8, 256>>>(fs2, fd2, esrc, edst, attn2, logits, EE);
        gat_aggregate_kernel<D2><<<NN, HH * D2>>>(fs2, logits, esrc, h2);
    }

    // ---- Global attention pooling ----
    gate_kernel<<<(NN * 32 + 255) / 256, 256>>>(h2, gw, gb, NN);
    pool_kernel<<<GG, 256>>>(h2, out);
}

// round 4
// speedup vs baseline: 1.6757x; 1.6757x over previous
#include <cuda_runtime.h>
#include <cuda_bf16.h>
#include <cstdint>

// ---------------------------------------------------------------------------
// Problem constants
// ---------------------------------------------------------------------------
#define NN      50000
#define EE      500000
#define GG      50
#define NPG     1000
#define INDIM   128
#define HH      4
#define D1      64
#define D2      128
#define SLOPE   0.2f

// ---------------------------------------------------------------------------
// Scratch
// ---------------------------------------------------------------------------
__device__ float g_fs1[NN * HH * D1];
__device__ float g_fd1[NN * HH * D1];
__device__ float g_h1 [NN * D1];
__device__ float g_fs2[NN * HH * D2];
__device__ float g_fd2[NN * HH * D2];
__device__ float g_h2 [NN * D2];
__device__ float g_gate[NN];

__device__ int g_counts[NN];
__device__ int g_incl[NN];
__device__ int g_bsum[64];
__device__ int g_boff[64];
__device__ int g_indptr[NN + 1];
__device__ int g_cursor[NN];
__device__ int g_csrc[EE];          // CSR-ordered source node ids

// ---------------------------------------------------------------------------
// Dual SGEMM with double buffering:
//   blocks with bx <  nbx : C0 = A@B0 + bias0
//   blocks with bx >= nbx : C1 = A@B1 + bias1
// BM=BN=128, BK=16, 256 threads, 8x8 microtile. Nn%128==0, K%16==0.
// ---------------------------------------------------------------------------
__global__ __launch_bounds__(256) void dual_sgemm_bias(
    const float* __restrict__ A,
    const float* __restrict__ B0, const float* __restrict__ bias0, float* __restrict__ C0,
    const float* __restrict__ B1, const float* __restrict__ bias1, float* __restrict__ C1,
    int M, int Nn, int K, int nbx)
{
    __shared__ float As[2][16][132];   // padded: kills STS conflicts
    __shared__ float Bs[2][16][128];

    int bx = blockIdx.x;
    const float* B; const float* bias; float* C;
    if (bx < nbx) { B = B0; bias = bias0; C = C0; }
    else          { B = B1; bias = bias1; C = C1; bx -= nbx; }

    const int tid = threadIdx.x;
    const int tx = tid & 15;
    const int ty = tid >> 4;
    const int row0 = blockIdx.y * 128;
    const int col0 = bx * 128;

    float acc[8][8];
#pragma unroll
    for (int i = 0; i < 8; i++)
#pragma unroll
        for (int j = 0; j < 8; j++) acc[i][j] = 0.f;

    float4 aS[2], bS[2];

    // prologue: load tile 0
#pragma unroll
    for (int r = 0; r < 2; r++) {
        int v = tid + r * 256;
        int m = v >> 2, kq = v & 3;
        int grow = row0 + m;
        aS[r] = (grow < M) ? *(const float4*)&A[(size_t)grow * K + kq * 4]
                           : make_float4(0.f, 0.f, 0.f, 0.f);
        int k = v >> 5, nq = v & 31;
        bS[r] = *(const float4*)&B[(size_t)k * Nn + col0 + nq * 4];
    }
#pragma unroll
    for (int r = 0; r < 2; r++) {
        int v = tid + r * 256;
        int m = v >> 2, kq = v & 3;
        As[0][kq * 4 + 0][m] = aS[r].x;
        As[0][kq * 4 + 1][m] = aS[r].y;
        As[0][kq * 4 + 2][m] = aS[r].z;
        As[0][kq * 4 + 3][m] = aS[r].w;
        int k = v >> 5, nq = v & 31;
        *(float4*)&Bs[0][k][nq * 4] = bS[r];
    }
    __syncthreads();

    const int nk = K >> 4;
    for (int kt = 0; kt < nk; kt++) {
        const int buf = kt & 1;
        if (kt + 1 < nk) {
            const int k0 = (kt + 1) << 4;
#pragma unroll
            for (int r = 0; r < 2; r++) {
                int v = tid + r * 256;
                int m = v >> 2, kq = v & 3;
                int grow = row0 + m;
                aS[r] = (grow < M) ? *(const float4*)&A[(size_t)grow * K + k0 + kq * 4]
                                   : make_float4(0.f, 0.f, 0.f, 0.f);
                int k = v >> 5, nq = v & 31;
                bS[r] = *(const float4*)&B[(size_t)(k0 + k) * Nn + col0 + nq * 4];
            }
        }
#pragma unroll
        for (int kk = 0; kk < 16; kk++) {
            float a[8], b[8];
            *(float4*)&a[0] = *(const float4*)&As[buf][kk][ty * 8];
            *(float4*)&a[4] = *(const float4*)&As[buf][kk][ty * 8 + 4];
            *(float4*)&b[0] = *(const float4*)&Bs[buf][kk][tx * 8];
            *(float4*)&b[4] = *(const float4*)&Bs[buf][kk][tx * 8 + 4];
#pragma unroll
            for (int i = 0; i < 8; i++)
#pragma unroll
                for (int j = 0; j < 8; j++) acc[i][j] += a[i] * b[j];
        }
        if (kt + 1 < nk) {
            const int nb = buf ^ 1;
#pragma unroll
            for (int r = 0; r < 2; r++) {
                int v = tid + r * 256;
                int m = v >> 2, kq = v & 3;
                As[nb][kq * 4 + 0][m] = aS[r].x;
                As[nb][kq * 4 + 1][m] = aS[r].y;
                As[nb][kq * 4 + 2][m] = aS[r].z;
                As[nb][kq * 4 + 3][m] = aS[r].w;
                int k = v >> 5, nq = v & 31;
                *(float4*)&Bs[nb][k][nq * 4] = bS[r];
            }
        }
        __syncthreads();
    }

#pragma unroll
    for (int i = 0; i < 8; i++) {
        int grow = row0 + ty * 8 + i;
        if (grow >= M) break;
#pragma unroll
        for (int j = 0; j < 8; j++) {
            int gcol = col0 + tx * 8 + j;
            C[(size_t)grow * Nn + gcol] = acc[i][j] + bias[gcol];
        }
    }
}

// ---------------------------------------------------------------------------
// CSR build by destination node
// ---------------------------------------------------------------------------
__global__ void zero_counts_kernel(int n) {
    int i = blockIdx.x * blockDim.x + threadIdx.x;
    if (i < n) g_counts[i] = 0;
}

__global__ void hist_kernel(const int* __restrict__ dst, int E) {
    int e = blockIdx.x * blockDim.x + threadIdx.x;
    if (e < E) atomicAdd(&g_counts[dst[e]], 1);
}

__global__ __launch_bounds__(1024) void scan_block_kernel(int n) {
    __shared__ int s[1024];
    int i = blockIdx.x * 1024 + threadIdx.x;
    s[threadIdx.x] = (i < n) ? g_counts[i] : 0;
    __syncthreads();
    for (int off = 1; off < 1024; off <<= 1) {
        int x = 0;
        if (threadIdx.x >= off) x = s[threadIdx.x - off];
        __syncthreads();
        s[threadIdx.x] += x;
        __syncthreads();
    }
    if (i < n) g_incl[i] = s[threadIdx.x];
    if (threadIdx.x == 1023) g_bsum[blockIdx.x] = s[1023];
}

__global__ void scan_bsum_kernel(int nb) {
    if (threadIdx.x == 0 && blockIdx.x == 0) {
        int acc = 0;
        for (int b = 0; b < nb; b++) { g_boff[b] = acc; acc += g_bsum[b]; }
    }
}

__global__ void finalize_indptr_kernel(int n) {
    int i = blockIdx.x * blockDim.x + threadIdx.x;
    if (i < n) {
        int v = g_incl[i] + g_boff[i >> 10];
        g_indptr[i + 1] = v;
    }
    if (i == 0) g_indptr[0] = 0;
}

__global__ void copy_cursor_kernel(int n) {
    int i = blockIdx.x * blockDim.x + threadIdx.x;
    if (i < n) g_cursor[i] = g_indptr[i];
}

__global__ void scatter_kernel(const int* __restrict__ dst,
                               const int* __restrict__ src, int E) {
    int e = blockIdx.x * blockDim.x + threadIdx.x;
    if (e < E) {
        int slot = atomicAdd(&g_cursor[dst[e]], 1);
        g_csrc[slot] = src[e];   // store src directly; no eid indirection
    }
}

// ---------------------------------------------------------------------------
// Fused GATv2 layer: per dst node, online-softmax over incoming edges.
// Block = 128 threads = 4 warps; warp h owns head h.
// Each fs[src] row is read exactly once and serves BOTH the logit
// computation and the weighted aggregation (kept in registers).
// Ends with the head max-pool.
// ---------------------------------------------------------------------------
template <int D>
__global__ __launch_bounds__(128) void gat_fused_kernel(
    const float* __restrict__ fs, const float* __restrict__ fd,
    const float* __restrict__ attn, float* __restrict__ hout)
{
    constexpr int J = D / 32;
    const int n = blockIdx.x;
    const int h = threadIdx.x >> 5;     // head = warp id
    const int lane = threadIdx.x & 31;

    const int beg = g_indptr[n];
    const int end = g_indptr[n + 1];

    float fdreg[J], areg[J], acc[J];
    const size_t rowbase = (size_t)n * (HH * D) + h * D + lane;
#pragma unroll
    for (int j = 0; j < J; j++) {
        fdreg[j] = fd[rowbase + 32 * j];
        areg[j]  = attn[h * D + lane + 32 * j];
        acc[j]   = 0.f;
    }
    float m = -1e30f, ssum = 0.f;

    for (int i = beg; i < end; i++) {
        const int s = g_csrc[i];
        const size_t sb = (size_t)s * (HH * D) + h * D + lane;
        float v[J];
        float p = 0.f;
#pragma unroll
        for (int j = 0; j < J; j++) {
            v[j] = fs[sb + 32 * j];
            float t = v[j] + fdreg[j];
            t = t > 0.f ? t : SLOPE * t;
            p = fmaf(areg[j], t, p);
        }
#pragma unroll
        for (int o = 16; o; o >>= 1) p += __shfl_xor_sync(0xffffffffu, p, o);

        // online softmax update
        float newm = fmaxf(m, p);
        float scale = __expf(m - newm);   // 0 on first edge (m=-1e30)
        float w = __expf(p - newm);
        ssum = ssum * scale + w;
#pragma unroll
        for (int j = 0; j < J; j++) acc[j] = acc[j] * scale + w * v[j];
        m = newm;
    }

    const float inv = ssum > 0.f ? 1.f / ssum : 0.f;

    __shared__ float red[HH * D];
#pragma unroll
    for (int j = 0; j < J; j++) red[h * D + lane + 32 * j] = acc[j] * inv;
    __syncthreads();

    if (threadIdx.x < D) {
        float mx = red[threadIdx.x];
#pragma unroll
        for (int hh = 1; hh < HH; hh++)
            mx = fmaxf(mx, red[hh * D + threadIdx.x]);
        hout[(size_t)n * D + threadIdx.x] = mx;
    }
}

// ---------------------------------------------------------------------------
// Gate: gate[n] = h2[n,:] . gate_w + gate_b  (one warp per node)
// ---------------------------------------------------------------------------
__global__ __launch_bounds__(256) void gate_kernel(
    const float* __restrict__ h2, const float* __restrict__ gw,
    const float* __restrict__ gb, int N)
{
    int warp = (blockIdx.x * blockDim.x + threadIdx.x) >> 5;
    int lane = threadIdx.x & 31;
    if (warp >= N) return;
    const float* p2 = h2 + (size_t)warp * D2;
    float p = 0.f;
#pragma unroll
    for (int d = lane; d < D2; d += 32) p = fmaf(p2[d], gw[d], p);
#pragma unroll
    for (int o = 16; o; o >>= 1) p += __shfl_down_sync(0xffffffffu, p, o);
    if (lane == 0) g_gate[warp] = p + gb[0];
}

// ---------------------------------------------------------------------------
// Global attention pooling: one block per graph (1000 contiguous nodes)
// ---------------------------------------------------------------------------
__global__ __launch_bounds__(256) void pool_kernel(
    const float* __restrict__ h2, float* __restrict__ out)
{
    const int g = blockIdx.x;
    const int t = threadIdx.x;
    __shared__ float red[256];
    __shared__ float w[NPG];
    const int base = g * NPG;

    float mm = -1e30f;
    for (int i = t; i < NPG; i += 256) mm = fmaxf(mm, g_gate[base + i]);
    red[t] = mm;
    __syncthreads();
    for (int o = 128; o; o >>= 1) {
        if (t < o) red[t] = fmaxf(red[t], red[t + o]);
        __syncthreads();
    }
    float gmax = red[0];
    __syncthreads();

    float ss = 0.f;
    for (int i = t; i < NPG; i += 256) {
        float e = __expf(g_gate[base + i] - gmax);
        w[i] = e;
        ss += e;
    }
    red[t] = ss;
    __syncthreads();
    for (int o = 128; o; o >>= 1) {
        if (t < o) red[t] += red[t + o];
        __syncthreads();
    }
    float inv = 1.f / red[0];
    __syncthreads();

    if (t < D2) {
        float acc = 0.f;
        for (int i = 0; i < NPG; i++)
            acc = fmaf(w[i], h2[(size_t)(base + i) * D2 + t], acc);
        out[g * D2 + t] = acc * inv;
    }
}

// ---------------------------------------------------------------------------
// Launch
// ---------------------------------------------------------------------------
extern "C" void kernel_launch(void* const* d_in, const int* in_sizes, int n_in,
                              void* d_out, int out_size)
{
    const float* x     = (const float*)d_in[0];
    const int*   esrc  = (const int*)  d_in[1];
    const int*   edst  = (const int*)  d_in[2];
    const float* Wl1   = (const float*)d_in[4];
    const float* bl1   = (const float*)d_in[5];
    const float* Wr1   = (const float*)d_in[6];
    const float* br1   = (const float*)d_in[7];
    const float* attn1 = (const float*)d_in[8];
    const float* Wl2   = (const float*)d_in[9];
    const float* bl2   = (const float*)d_in[10];
    const float* Wr2   = (const float*)d_in[11];
    const float* br2   = (const float*)d_in[12];
    const float* attn2 = (const float*)d_in[13];
    const float* gw    = (const float*)d_in[14];
    const float* gb    = (const float*)d_in[15];
    float* out = (float*)d_out;

    float *fs1, *fd1, *h1, *fs2, *fd2, *h2;
    cudaGetSymbolAddress((void**)&fs1, g_fs1);
    cudaGetSymbolAddress((void**)&fd1, g_fd1);
    cudaGetSymbolAddress((void**)&h1,  g_h1);
    cudaGetSymbolAddress((void**)&fs2, g_fs2);
    cudaGetSymbolAddress((void**)&fd2, g_fd2);
    cudaGetSymbolAddress((void**)&h2,  g_h2);

    const int M = NN;

    // ---- CSR build (shared by both layers) ----
    zero_counts_kernel<<<(NN + 255) / 256, 256>>>(NN);
    hist_kernel<<<(EE + 255) / 256, 256>>>(edst, EE);
    int nb = (NN + 1023) / 1024;
    scan_block_kernel<<<nb, 1024>>>(NN);
    scan_bsum_kernel<<<1, 32>>>(nb);
    finalize_indptr_kernel<<<(NN + 255) / 256, 256>>>(NN);
    copy_cursor_kernel<<<(NN + 255) / 256, 256>>>(NN);
    scatter_kernel<<<(EE + 255) / 256, 256>>>(edst, esrc, EE);

    // ---- Layer 1: fs1/fd1 in one launch, then fused GAT ----
    {
        const int Nn = HH * D1;               // 256
        dim3 grid(2 * (Nn / 128), (M + 127) / 128);
        dual_sgemm_bias<<<grid, 256>>>(x, Wl1, bl1, fs1, Wr1, br1, fd1,
                                       M, Nn, INDIM, Nn / 128);
        gat_fused_kernel<D1><<<NN, 128>>>(fs1, fd1, attn1, h1);
    }

    // ---- Layer 2 ----
    {
        const int Nn = HH * D2;               // 512
        dim3 grid(2 * (Nn / 128), (M + 127) / 128);
        dual_sgemm_bias<<<grid, 256>>>(h1, Wl2, bl2, fs2, Wr2, br2, fd2,
                                       M, Nn, D1, Nn / 128);
        gat_fused_kernel<D2><<<NN, 128>>>(fs2, fd2, attn2, h2);
    }

    // ---- Global attention pooling ----
    gate_kernel<<<(NN * 32 + 255) / 256, 256>>>(h2, gw, gb, NN);
    pool_kernel<<<GG, 256>>>(h2, out);
}